// round 2
// baseline (speedup 1.0000x reference)
#include <cuda_runtime.h>
#include <cuda_bf16.h>
#include <math.h>

// Problem constants
#define N_TOK 16384
#define D_IN  1024
#define D_OUT 1024
#define N_EXP 8
#define RANK  16
#define TOPK  2
#define SCALING (32.0f / 16.0f)   // ALPHA / R = 2.0

// Scratch: per-token gated+scaled low-rank activations and expert ids.
// hh[n][k*16+r] = SCALING * weight_k * sum_d tokens[n][d] * A[e_k][d][r]
__device__ float g_hh[(size_t)N_TOK * 32];
__device__ int   g_eid[(size_t)N_TOK * 2];

// ---------------------------------------------------------------------------
// Kernel 1: router (logits, top-2, softmax) + low-rank h for selected experts
// One block per token, 256 threads (8 warps).
// ---------------------------------------------------------------------------
__global__ __launch_bounds__(256) void router_h_kernel(
    const float* __restrict__ tokens,   // [N, D_IN]
    const float* __restrict__ A,        // [E, D_IN, R]
    const float* __restrict__ Wg,       // [D_IN, E]
    float* __restrict__ out_logits,     // [N, E]
    float* __restrict__ out_sel,        // [N, K] (as float)
    float* __restrict__ out_wts)        // [N, K]
{
    const int n    = blockIdx.x;
    const int tid  = threadIdx.x;
    const int w    = tid >> 5;
    const int lane = tid & 31;

    __shared__ float t_s[D_IN];
    __shared__ float logits_s[N_EXP];
    __shared__ float part_s[8][16];
    __shared__ int   eid_s[2];
    __shared__ float scale_s[2];

    const float* trow = tokens + (size_t)n * D_IN;
    for (int i = tid; i < D_IN; i += 256) t_s[i] = trow[i];
    __syncthreads();

    // --- Phase 1: logits. Warp w computes logit for expert w. ---
    float acc = 0.f;
    for (int d = lane; d < D_IN; d += 32)
        acc += t_s[d] * Wg[d * N_EXP + w];
    #pragma unroll
    for (int off = 16; off; off >>= 1)
        acc += __shfl_xor_sync(0xffffffffu, acc, off);
    if (lane == 0) logits_s[w] = acc;
    __syncthreads();

    // --- Phase 2: top-2 + softmax (thread 0), write router outputs ---
    if (tid == 0) {
        int i0 = 0; float v0 = logits_s[0];
        #pragma unroll
        for (int e = 1; e < N_EXP; e++)
            if (logits_s[e] > v0) { v0 = logits_s[e]; i0 = e; }
        int i1 = -1; float v1 = -INFINITY;
        #pragma unroll
        for (int e = 0; e < N_EXP; e++)
            if (e != i0 && logits_s[e] > v1) { v1 = logits_s[e]; i1 = e; }
        float e1v   = __expf(v1 - v0);
        float denom = 1.0f + e1v;
        float p0 = 1.0f / denom;
        float p1 = e1v / denom;
        out_sel[(size_t)n * TOPK + 0] = (float)i0;
        out_sel[(size_t)n * TOPK + 1] = (float)i1;
        out_wts[(size_t)n * TOPK + 0] = p0;
        out_wts[(size_t)n * TOPK + 1] = p1;
        eid_s[0]   = i0;       eid_s[1]   = i1;
        scale_s[0] = SCALING * p0;
        scale_s[1] = SCALING * p1;
        g_eid[(size_t)n * 2 + 0] = i0;
        g_eid[(size_t)n * 2 + 1] = i1;
    }
    if (tid < N_EXP) out_logits[(size_t)n * N_EXP + tid] = logits_s[tid];
    __syncthreads();

    // --- Phase 3: h[k][r] = sum_d t[d] * A[e_k][d][r] for 2 selected experts
    // Warps 0-3 -> expert slot 0, warps 4-7 -> slot 1; each warp a 256-d slice.
    const int k = w >> 2;
    const int q = w & 3;
    const int e = eid_s[k];
    const float* Abase = A + (size_t)e * D_IN * RANK;

    float a16[16];
    #pragma unroll
    for (int r = 0; r < 16; r++) a16[r] = 0.f;

    #pragma unroll
    for (int it = 0; it < 8; it++) {
        int d = q * 256 + it * 32 + lane;
        float tv = t_s[d];
        const float4* ap = (const float4*)(Abase + (size_t)d * RANK);
        float4 a0 = ap[0], a1 = ap[1], a2 = ap[2], a3 = ap[3];
        a16[0]  += tv * a0.x;  a16[1]  += tv * a0.y;
        a16[2]  += tv * a0.z;  a16[3]  += tv * a0.w;
        a16[4]  += tv * a1.x;  a16[5]  += tv * a1.y;
        a16[6]  += tv * a1.z;  a16[7]  += tv * a1.w;
        a16[8]  += tv * a2.x;  a16[9]  += tv * a2.y;
        a16[10] += tv * a2.z;  a16[11] += tv * a2.w;
        a16[12] += tv * a3.x;  a16[13] += tv * a3.y;
        a16[14] += tv * a3.z;  a16[15] += tv * a3.w;
    }
    // reduce 16 values across the warp
    #pragma unroll
    for (int off = 16; off; off >>= 1) {
        #pragma unroll
        for (int r = 0; r < 16; r++)
            a16[r] += __shfl_xor_sync(0xffffffffu, a16[r], off);
    }
    if (lane == 0) {
        #pragma unroll
        for (int r = 0; r < 16; r++) part_s[w][r] = a16[r];
    }
    __syncthreads();
    if (tid < 32) {
        int k2 = tid >> 4, r = tid & 15;
        float s = part_s[k2 * 4 + 0][r] + part_s[k2 * 4 + 1][r] +
                  part_s[k2 * 4 + 2][r] + part_s[k2 * 4 + 3][r];
        g_hh[(size_t)n * 32 + k2 * 16 + r] = s * scale_s[k2];
    }
}

// ---------------------------------------------------------------------------
// Kernel 2: base GEMM (tokens @ W_base) with fused LoRA epilogue.
// 128x128 tile, BK=16, 256 threads, 8x8 per-thread microtile, fp32.
// ---------------------------------------------------------------------------
#define BM 128
#define BN 128
#define BK 16

__global__ __launch_bounds__(256, 2) void gemm_lora_kernel(
    const float* __restrict__ T,      // [N, D_IN]
    const float* __restrict__ W,      // [D_IN, D_OUT]
    const float* __restrict__ Bm,     // [E, R, D_OUT]
    float* __restrict__ out)          // [N, D_OUT]
{
    __shared__ float As[BK][BM + 4];
    __shared__ float Bs[BK][BN];
    __shared__ float hh_s[BM * 32];
    __shared__ int   eid_sh[BM * 2];

    const int bm = blockIdx.y * BM;
    const int bn = blockIdx.x * BN;
    const int tid = threadIdx.x;
    const int tx = tid & 15;   // col group
    const int ty = tid >> 4;   // row group

    // stage per-row LoRA data (independent of main loop; covered by first sync)
    for (int i = tid; i < BM * 32; i += 256)
        hh_s[i] = g_hh[(size_t)bm * 32 + i];
    for (int i = tid; i < BM * 2; i += 256)
        eid_sh[i] = g_eid[(size_t)bm * 2 + i];

    float acc[8][8];
    #pragma unroll
    for (int i = 0; i < 8; i++)
        #pragma unroll
        for (int j = 0; j < 8; j++) acc[i][j] = 0.f;

    for (int k0 = 0; k0 < D_IN; k0 += BK) {
        // Load A tile (tokens), store transposed As[k][m]
        #pragma unroll
        for (int i = 0; i < 2; i++) {
            int idx = tid + i * 256;          // 0..511 float4s
            int row = idx >> 2;               // 0..127
            int c4  = idx & 3;                // 0..3
            float4 v = *(const float4*)(T + (size_t)(bm + row) * D_IN + k0 + c4 * 4);
            As[c4 * 4 + 0][row] = v.x;
            As[c4 * 4 + 1][row] = v.y;
            As[c4 * 4 + 2][row] = v.z;
            As[c4 * 4 + 3][row] = v.w;
        }
        // Load B tile (W_base) Bs[k][n]
        #pragma unroll
        for (int i = 0; i < 2; i++) {
            int idx = tid + i * 256;          // 0..511 float4s
            int row = idx >> 5;               // 0..15
            int c4  = idx & 31;               // 0..31
            *(float4*)&Bs[row][c4 * 4] =
                *(const float4*)(W + (size_t)(k0 + row) * D_OUT + bn + c4 * 4);
        }
        __syncthreads();

        #pragma unroll
        for (int kk = 0; kk < BK; kk++) {
            float ra[8], rb[8];
            *(float4*)&ra[0] = *(const float4*)&As[kk][ty * 8];
            *(float4*)&ra[4] = *(const float4*)&As[kk][ty * 8 + 4];
            *(float4*)&rb[0] = *(const float4*)&Bs[kk][tx * 8];
            *(float4*)&rb[4] = *(const float4*)&Bs[kk][tx * 8 + 4];
            #pragma unroll
            for (int i = 0; i < 8; i++)
                #pragma unroll
                for (int j = 0; j < 8; j++)
                    acc[i][j] += ra[i] * rb[j];
        }
        __syncthreads();
    }

    // ---- LoRA epilogue: acc[i][:] += sum_{j<32} hh[row][j] * B[e][r][m] ----
    const int mcol = bn + tx * 8;
    #pragma unroll
    for (int i = 0; i < 8; i++) {
        int lr = ty * 8 + i;
        int e0 = eid_sh[lr * 2 + 0];
        int e1 = eid_sh[lr * 2 + 1];
        const float* B0 = Bm + (size_t)e0 * RANK * D_OUT + mcol;
        const float* B1 = Bm + (size_t)e1 * RANK * D_OUT + mcol;
        const float* hrow = &hh_s[lr * 32];
        #pragma unroll
        for (int r = 0; r < RANK; r++) {
            float h0 = hrow[r];
            float4 b0a = *(const float4*)(B0 + (size_t)r * D_OUT);
            float4 b0b = *(const float4*)(B0 + (size_t)r * D_OUT + 4);
            acc[i][0] += h0 * b0a.x; acc[i][1] += h0 * b0a.y;
            acc[i][2] += h0 * b0a.z; acc[i][3] += h0 * b0a.w;
            acc[i][4] += h0 * b0b.x; acc[i][5] += h0 * b0b.y;
            acc[i][6] += h0 * b0b.z; acc[i][7] += h0 * b0b.w;
            float h1 = hrow[16 + r];
            float4 b1a = *(const float4*)(B1 + (size_t)r * D_OUT);
            float4 b1b = *(const float4*)(B1 + (size_t)r * D_OUT + 4);
            acc[i][0] += h1 * b1a.x; acc[i][1] += h1 * b1a.y;
            acc[i][2] += h1 * b1a.z; acc[i][3] += h1 * b1a.w;
            acc[i][4] += h1 * b1b.x; acc[i][5] += h1 * b1b.y;
            acc[i][6] += h1 * b1b.z; acc[i][7] += h1 * b1b.w;
        }
    }

    // ---- write out ----
    #pragma unroll
    for (int i = 0; i < 8; i++) {
        float* orow = out + (size_t)(bm + ty * 8 + i) * D_OUT + mcol;
        *(float4*)orow       = *(float4*)&acc[i][0];
        *(float4*)(orow + 4) = *(float4*)&acc[i][4];
    }
}

// ---------------------------------------------------------------------------
extern "C" void kernel_launch(void* const* d_in, const int* in_sizes, int n_in,
                              void* d_out, int out_size) {
    const float* tokens = (const float*)d_in[0];
    const float* W_base = (const float*)d_in[1];
    const float* A      = (const float*)d_in[2];
    const float* B      = (const float*)d_in[3];
    const float* W_gate = (const float*)d_in[4];

    float* out        = (float*)d_out;                       // [N, D_OUT]
    float* out_logits = out + (size_t)N_TOK * D_OUT;         // [N, E]
    float* out_sel    = out_logits + (size_t)N_TOK * N_EXP;  // [N, K]
    float* out_wts    = out_sel + (size_t)N_TOK * TOPK;      // [N, K]

    router_h_kernel<<<N_TOK, 256>>>(tokens, A, W_gate,
                                    out_logits, out_sel, out_wts);

    dim3 grid(D_OUT / BN, N_TOK / BM);
    gemm_lora_kernel<<<grid, 256>>>(tokens, W_base, B, out);
}